// round 14
// baseline (speedup 1.0000x reference)
#include <cuda_runtime.h>
#include <cuda_bf16.h>
#include <math_constants.h>

// ProbAttention (Informer ProbSparse) — B=4, L=S=2048, H=8, D=64, sample_k=n_top=40.
// Inputs: queries f32 [B,L,H,D], keys f32 [B,S,H,D], values f32 [B,S,H,D],
//         index_sample i32 [L,40].  Output f32 [B,L,H,D].

#define B_ 4
#define L_ 2048
#define S_ 2048
#define H_ 8
#define D_ 64
#define SK_ 40
#define NTOP_ 40
#define BH_ (B_ * H_)
#define SCALE_ 0.125f
#define QPB_ 4
#define QBLKS_ (NTOP_ / QPB_)        // 10

#define CHUNK_ 256
#define NCHUNK_ (L_ / CHUNK_)        // 8
#define TILE2_ 256                   // k-rows per smem tile (k_sample)
#define ATILE_ 256                   // k-rows per smem tile (k_attn)

// Scratch
__device__ unsigned short g_sorted[L_ * SK_];   // per-l samples, ascending s
__device__ float g_M[BH_ * L_];
__device__ int   g_top[BH_ * NTOP_];
__device__ float g_vmean[BH_ * D_];

// Order-preserving float->uint (kept for topk packing)
__device__ __forceinline__ unsigned ford(float f) {
    unsigned u = __float_as_uint(f);
    return (u & 0x80000000u) ? ~u : (u | 0x80000000u);
}

// Packed f32x2 helpers (Blackwell)
__device__ __forceinline__ unsigned long long ffma2(unsigned long long a,
                                                    unsigned long long b,
                                                    unsigned long long c) {
    unsigned long long d;
    asm("fma.rn.f32x2 %0, %1, %2, %3;" : "=l"(d) : "l"(a), "l"(b), "l"(c));
    return d;
}
__device__ __forceinline__ float f32x2_sum(unsigned long long v) {
    float lo, hi;
    asm("mov.b64 {%0, %1}, %2;" : "=f"(lo), "=f"(hi) : "l"(v));
    return lo + hi;
}

// ---------------------------------------------------------------------------
// K_sort: one WARP per l. Rank sort (all-pairs, stable) of 40 sample indices
// -> g_sorted[l][0..39] ascending. Replaces histogram/scan/scatter entirely.
// ---------------------------------------------------------------------------
__global__ __launch_bounds__(256) void k_sort(const int* __restrict__ idxs) {
    const int l = (blockIdx.x << 3) + (threadIdx.x >> 5);   // grid 256 x 8 warps
    const int lane = threadIdx.x & 31;

    int s0v = idxs[l * SK_ + lane];                          // u = lane
    int s1v = (lane < SK_ - 32) ? idxs[l * SK_ + 32 + lane] : 0x7FFFFFFF;

    int r0 = 0, r1 = 0;
    #pragma unroll
    for (int v = 0; v < SK_; v++) {
        int sv = __shfl_sync(0xFFFFFFFFu, (v < 32) ? s0v : s1v, v & 31);
        r0 += (sv < s0v) || (sv == s0v && v < lane);
        r1 += (sv < s1v) || (sv == s1v && v < 32 + lane);
    }
    unsigned short* row = g_sorted + l * SK_;
    row[r0] = (unsigned short)s0v;
    if (lane < SK_ - 32) row[r1] = (unsigned short)s1v;
}

// ---------------------------------------------------------------------------
// K1 v2: block = (b,h,chunk); thread t owns l = chunk*256+t.
//  - q-row in REGISTERS, lane-rotated (static indexing)
//  - K streamed in 256-row smem tiles; per-pair read = 16 LDS.128,
//    conflict-free for random rows via col (i+lane)&15 rotation
//  - per-l max/sum in registers (no atomics); sorted sample list -> ptr walk
// smem: k/q staging 64KB + sidx 21KB = 85.5KB -> 2 blocks/SM.
// ---------------------------------------------------------------------------
#define SMEM_SAMPLE_ (TILE2_ * D_ * 4 + CHUNK_ * 42 * 2)

__global__ __launch_bounds__(256) void k_sample(const float* __restrict__ q,
                                                const float* __restrict__ k) {
    extern __shared__ float dyn[];
    float* kt = dyn;                                       // [256][64] plain
    unsigned short* sidx = (unsigned short*)(dyn + TILE2_ * D_); // [256][42] pad

    const int bhc = blockIdx.x;
    const int c = bhc & 7, h = (bhc >> 3) & 7, b = bhc >> 6;
    const int t = threadIdx.x;
    const int lane = t & 31;

    // Load sorted sample lists for this chunk (u32 pairs -> padded u16 rows)
    {
        const unsigned* gs = (const unsigned*)g_sorted;
        unsigned* srows = (unsigned*)sidx;
        for (int i = t; i < CHUNK_ * (SK_ / 2); i += 256) {
            int lr = i / (SK_ / 2), w = i % (SK_ / 2);
            srows[lr * 21 + w] = gs[(size_t)(c * CHUNK_ + lr) * (SK_ / 2) + w];
        }
    }

    // Stage q-chunk into kt (coalesced), then read own row rotated into regs
    {
        const float4* qg = (const float4*)q;
        for (int i = t; i < CHUNK_ * 16; i += 256) {
            int lr = i >> 4, j = i & 15;
            ((float4*)kt)[lr * 16 + j] =
                qg[(size_t)((b * L_ + (c * CHUNK_ + lr)) * H_ + h) * 16 + j];
        }
    }
    __syncthreads();

    ulonglong2 qreg[16];
    {
        const ulonglong2* kt2 = (const ulonglong2*)kt;
        #pragma unroll
        for (int i = 0; i < 16; i++)
            qreg[i] = kt2[t * 16 + ((i + lane) & 15)];
    }

    const unsigned short* srow = sidx + t * 42;
    const float4* kg = (const float4*)k;
    float mx = -CUDART_INF_F, sm = 0.f;
    int p = 0;

    for (int s0 = 0; s0 < S_; s0 += TILE2_) {
        __syncthreads();                 // all q-reg reads / prior tile done
        for (int i = t; i < TILE2_ * 16; i += 256) {
            int r = i >> 4, j = i & 15;
            ((float4*)kt)[r * 16 + j] =
                kg[(size_t)((b * S_ + (s0 + r)) * H_ + h) * 16 + j];
        }
        __syncthreads();

        const ulonglong2* kt2 = (const ulonglong2*)kt;
        while (p < SK_) {
            int s = srow[p];
            if (s >= s0 + TILE2_) break;
            int sr = s - s0;
            unsigned long long a2 = 0ull;
            #pragma unroll
            for (int i = 0; i < 16; i++) {
                ulonglong2 kv = kt2[sr * 16 + ((i + lane) & 15)];
                a2 = ffma2(qreg[i].x, kv.x, a2);
                a2 = ffma2(qreg[i].y, kv.y, a2);
            }
            float acc = f32x2_sum(a2);
            mx = fmaxf(mx, acc);
            sm += acc;
            p++;
        }
    }

    g_M[(size_t)(b * H_ + h) * L_ + c * CHUNK_ + t] =
        mx - sm * (1.0f / (float)S_);
}

// ---------------------------------------------------------------------------
// K2: top-40 per (b,h). One WARP per bh; 64 vals/lane register-resident;
// iterative argmax via 64-bit shuffle keys; tie -> smaller index.
// ---------------------------------------------------------------------------
__global__ __launch_bounds__(512) void k_topk() {
    const int w = (blockIdx.x << 4) + (threadIdx.x >> 5);  // bh 0..31
    const int lane = threadIdx.x & 31;

    float vals[64];
    #pragma unroll
    for (int j = 0; j < 64; j++)
        vals[j] = g_M[(size_t)w * L_ + j * 32 + lane];

    unsigned long long mask = 0ull;
    float bv = -CUDART_INF_F; int bj = 0;
    #pragma unroll
    for (int j = 0; j < 64; j++)
        if (vals[j] > bv) { bv = vals[j]; bj = j; }

    for (int it = 0; it < NTOP_; it++) {
        unsigned long long key =
            ((unsigned long long)ford(bv) << 32) |
            (unsigned)~(unsigned)(bj * 32 + lane);
        #pragma unroll
        for (int o = 16; o; o >>= 1) {
            unsigned long long ot = __shfl_xor_sync(0xFFFFFFFFu, key, o);
            if (ot > key) key = ot;
        }
        unsigned widx = ~(unsigned)(key & 0xFFFFFFFFu);
        if (lane == 0) g_top[w * NTOP_ + it] = (int)widx;
        if ((widx & 31u) == (unsigned)lane) {
            mask |= 1ull << (widx >> 5);
            bv = -CUDART_INF_F; bj = 0;
            #pragma unroll
            for (int j = 0; j < 64; j++)
                if (!((mask >> j) & 1ull) && vals[j] > bv) { bv = vals[j]; bj = j; }
        }
    }
}

// ---------------------------------------------------------------------------
// K3: vmean[bh, d] = mean_s v[b,s,h,d]
// ---------------------------------------------------------------------------
__global__ void k_vmean(const float* __restrict__ v) {
    int bh = blockIdx.x;
    int b = bh >> 3, h = bh & 7;
    int tid = threadIdx.x;
    int d = tid & 63, g = tid >> 6;
    float s = 0.f;
    #pragma unroll 4
    for (int r = g; r < S_; r += 4)
        s += v[(((size_t)(b * S_ + r)) * H_ + h) * D_ + d];
    __shared__ float part[4][D_];
    part[g][d] = s;
    __syncthreads();
    if (g == 0)
        g_vmean[bh * D_ + d] =
            (part[0][d] + part[1][d] + part[2][d] + part[3][d]) * (1.0f / (float)S_);
}

// ---------------------------------------------------------------------------
// K4: out[b,l,h,d] = vmean[bh,d]
// ---------------------------------------------------------------------------
__global__ void k_fill(float4* __restrict__ out) {
    unsigned i = blockIdx.x * blockDim.x + threadIdx.x;
    if (i >= (unsigned)(B_ * L_ * H_ * (D_ / 4))) return;
    unsigned d4 = i & 15u;
    unsigned h  = (i >> 4) & 7u;
    unsigned b  = i >> 18;
    const float4* vm = (const float4*)g_vmean;
    out[i] = __ldg(vm + ((b * H_ + h) * (D_ / 4) + d4));
}

// ---------------------------------------------------------------------------
// K5: dense attention (proven R10 version): 4 queries/block, 320 blocks,
// smem-tiled K scores, warp softmax, coalesced AV.
// Dyn smem: 64KB.
// ---------------------------------------------------------------------------
#define SMEM_ATTN_ (ATILE_ * D_ * 4)

__global__ __launch_bounds__(256) void k_attn(const float* __restrict__ q,
                                              const float* __restrict__ k,
                                              const float* __restrict__ v,
                                              float* __restrict__ out) {
    extern __shared__ float k_t[];          // [ATILE_][16 float4] swizzled
    int bh = blockIdx.x / QBLKS_;
    int qb = blockIdx.x % QBLKS_;
    int b = bh >> 3, h = bh & 7;
    int tid = threadIdx.x;

    __shared__ float sq[QPB_][D_];
    __shared__ float sc[QPB_][S_];          // 32 KB
    __shared__ float sZ[QPB_];
    __shared__ int   sl[QPB_];
    __shared__ float pr[4][QPB_][D_];

    if (tid < QPB_ * D_) {
        int qi = tid >> 6, d = tid & 63;
        int lsel = g_top[bh * NTOP_ + qb * QPB_ + qi];
        if (d == 0) sl[qi] = lsel;
        sq[qi][d] = q[(((size_t)(b * L_ + lsel)) * H_ + h) * D_ + d] * SCALE_;
    }
    __syncthreads();

    const float4* kg = (const float4*)k;
    for (int s0 = 0; s0 < S_; s0 += ATILE_) {
        __syncthreads();
        for (int i = tid; i < ATILE_ * 16; i += 256) {
            int r = i >> 4, j = i & 15;
            ((float4*)k_t)[r * 16 + (j ^ (r & 15))] =
                kg[(size_t)((b * S_ + (s0 + r)) * H_ + h) * 16 + j];
        }
        __syncthreads();

        int r = tid;
        const float4* kr = (const float4*)k_t + r * 16;
        const float4* q0 = (const float4*)sq[0];
        const float4* q1 = (const float4*)sq[1];
        const float4* q2 = (const float4*)sq[2];
        const float4* q3 = (const float4*)sq[3];
        float a0 = 0.f, a1 = 0.f, a2 = 0.f, a3 = 0.f;
        #pragma unroll
        for (int j = 0; j < 16; j++) {
            float4 kv = kr[j ^ (r & 15)];
            float4 qa = q0[j];
            a0 += qa.x * kv.x + qa.y * kv.y + qa.z * kv.z + qa.w * kv.w;
            float4 qc = q1[j];
            a1 += qc.x * kv.x + qc.y * kv.y + qc.z * kv.z + qc.w * kv.w;
            float4 qd = q2[j];
            a2 += qd.x * kv.x + qd.y * kv.y + qd.z * kv.z + qd.w * kv.w;
            float4 qe = q3[j];
            a3 += qe.x * kv.x + qe.y * kv.y + qe.z * kv.z + qe.w * kv.w;
        }
        sc[0][s0 + r] = a0;
        sc[1][s0 + r] = a1;
        sc[2][s0 + r] = a2;
        sc[3][s0 + r] = a3;
    }
    __syncthreads();

    int w = tid >> 5, lane = tid & 31;
    if (w < QPB_) {
        float mx = -CUDART_INF_F;
        for (int s = lane; s < S_; s += 32) mx = fmaxf(mx, sc[w][s]);
        #pragma unroll
        for (int o = 16; o; o >>= 1) mx = fmaxf(mx, __shfl_xor_sync(0xFFFFFFFFu, mx, o));
        float sum = 0.f;
        for (int s = lane; s < S_; s += 32) {
            float e = __expf(sc[w][s] - mx);
            sc[w][s] = e;
            sum += e;
        }
        #pragma unroll
        for (int o = 16; o; o >>= 1) sum += __shfl_xor_sync(0xFFFFFFFFu, sum, o);
        if (lane == 0) sZ[w] = sum;
    }
    __syncthreads();

    int d = tid & 63, g = tid >> 6;
    float acc[QPB_] = {0.f, 0.f, 0.f, 0.f};
    #pragma unroll 4
    for (int s = g; s < S_; s += 4) {
        float vv = v[(((size_t)(b * S_ + s)) * H_ + h) * D_ + d];
        #pragma unroll
        for (int qi = 0; qi < QPB_; qi++) acc[qi] += sc[qi][s] * vv;
    }
    #pragma unroll
    for (int qi = 0; qi < QPB_; qi++) pr[g][qi][d] = acc[qi];
    __syncthreads();
    if (g < QPB_) {
        int qi = g;
        float r = (pr[0][qi][d] + pr[1][qi][d] + pr[2][qi][d] + pr[3][qi][d]) / sZ[qi];
        out[(((size_t)(b * L_ + sl[qi])) * H_ + h) * D_ + d] = r;
    }
}

// ---------------------------------------------------------------------------
extern "C" void kernel_launch(void* const* d_in, const int* in_sizes, int n_in,
                              void* d_out, int out_size) {
    const float* q   = (const float*)d_in[0];
    const float* k   = (const float*)d_in[1];
    const float* v   = (const float*)d_in[2];
    const int*   idx = (const int*)d_in[3];
    float* out = (float*)d_out;

    cudaFuncSetAttribute(k_sample, cudaFuncAttributeMaxDynamicSharedMemorySize,
                         SMEM_SAMPLE_);
    cudaFuncSetAttribute(k_attn, cudaFuncAttributeMaxDynamicSharedMemorySize,
                         SMEM_ATTN_);

    // 1: vmean  2: fill  3: sort  4: sample (ncu capture slot)  5: topk  6: attn
    k_vmean<<<BH_, 256>>>(v);
    {
        unsigned n4 = B_ * L_ * H_ * (D_ / 4);
        k_fill<<<(n4 + 255) / 256, 256>>>((float4*)out);
    }
    k_sort<<<L_ / 8, 256>>>(idx);
    k_sample<<<B_ * H_ * NCHUNK_, 256, SMEM_SAMPLE_>>>(q, k);
    k_topk<<<2, 512>>>();
    k_attn<<<BH_ * QBLKS_, 256, SMEM_ATTN_>>>(q, k, v, out);
}

// round 15
// speedup vs baseline: 1.5395x; 1.5395x over previous
#include <cuda_runtime.h>
#include <cuda_bf16.h>
#include <math_constants.h>

// ProbAttention (Informer ProbSparse) — B=4, L=S=2048, H=8, D=64, sample_k=n_top=40.
// Inputs: queries f32 [B,L,H,D], keys f32 [B,S,H,D], values f32 [B,S,H,D],
//         index_sample i32 [L,40].  Output f32 [B,L,H,D].

#define B_ 4
#define L_ 2048
#define S_ 2048
#define H_ 8
#define D_ 64
#define SK_ 40
#define NTOP_ 40
#define BH_ (B_ * H_)
#define SCALE_ 0.125f
#define QPB_ 4
#define QBLKS_ (NTOP_ / QPB_)        // 10

#define CHUNK_ 256
#define NCHUNK_ (L_ / CHUNK_)        // 8
#define TILE2_ 256                   // k-rows per smem tile (k_sample)
#define ATILE_ 256                   // k-rows per smem tile (k_attn)

// Scratch
__device__ unsigned short g_sorted[L_ * SK_];   // per-l samples, ascending s
__device__ float g_M[BH_ * L_];
__device__ int   g_top[BH_ * NTOP_];
__device__ float g_vmean[BH_ * D_];

// Order-preserving float->uint (topk packing)
__device__ __forceinline__ unsigned ford(float f) {
    unsigned u = __float_as_uint(f);
    return (u & 0x80000000u) ? ~u : (u | 0x80000000u);
}

// Packed f32x2 helpers (Blackwell)
__device__ __forceinline__ unsigned long long ffma2(unsigned long long a,
                                                    unsigned long long b,
                                                    unsigned long long c) {
    unsigned long long d;
    asm("fma.rn.f32x2 %0, %1, %2, %3;" : "=l"(d) : "l"(a), "l"(b), "l"(c));
    return d;
}
__device__ __forceinline__ unsigned long long addf2(unsigned long long a,
                                                    unsigned long long b) {
    unsigned long long d;
    asm("add.rn.f32x2 %0, %1, %2;" : "=l"(d) : "l"(a), "l"(b));
    return d;
}
__device__ __forceinline__ float f32x2_sum(unsigned long long v) {
    float lo, hi;
    asm("mov.b64 {%0, %1}, %2;" : "=f"(lo), "=f"(hi) : "l"(v));
    return lo + hi;
}

// ---------------------------------------------------------------------------
// K_sort: one WARP per l. Stable rank sort of 40 sample indices -> ascending.
// ---------------------------------------------------------------------------
__global__ __launch_bounds__(256) void k_sort(const int* __restrict__ idxs) {
    const int l = (blockIdx.x << 3) + (threadIdx.x >> 5);
    const int lane = threadIdx.x & 31;

    int s0v = idxs[l * SK_ + lane];
    int s1v = (lane < SK_ - 32) ? idxs[l * SK_ + 32 + lane] : 0x7FFFFFFF;

    int r0 = 0, r1 = 0;
    #pragma unroll
    for (int v = 0; v < SK_; v++) {
        int sv = __shfl_sync(0xFFFFFFFFu, (v < 32) ? s0v : s1v, v & 31);
        r0 += (sv < s0v) || (sv == s0v && v < lane);
        r1 += (sv < s1v) || (sv == s1v && v < 32 + lane);
    }
    unsigned short* row = g_sorted + l * SK_;
    row[r0] = (unsigned short)s0v;
    if (lane < SK_ - 32) row[r1] = (unsigned short)s1v;
}

// ---------------------------------------------------------------------------
// K1: block = (b,h,chunk); thread t owns l = chunk*256+t.
// q-row in registers (lane-rotated); K streamed in 256-row smem tiles;
// conflict-free random-row LDS via (i+lane)&15 rotation; per-l max/sum in
// registers. THIS ROUND: 4 independent f32x2 accumulators (break the
// 32-deep FFMA dependency chain that made R14 latency-bound).
// ---------------------------------------------------------------------------
#define SMEM_SAMPLE_ (TILE2_ * D_ * 4 + CHUNK_ * 42 * 2)

__global__ __launch_bounds__(256) void k_sample(const float* __restrict__ q,
                                                const float* __restrict__ k) {
    extern __shared__ float dyn[];
    float* kt = dyn;                                             // [256][64]
    unsigned short* sidx = (unsigned short*)(dyn + TILE2_ * D_); // [256][42]

    const int bhc = blockIdx.x;
    const int c = bhc & 7, h = (bhc >> 3) & 7, b = bhc >> 6;
    const int t = threadIdx.x;
    const int lane = t & 31;

    // Sorted sample lists for this chunk (u32 pairs -> padded u16 rows)
    {
        const unsigned* gs = (const unsigned*)g_sorted;
        unsigned* srows = (unsigned*)sidx;
        for (int i = t; i < CHUNK_ * (SK_ / 2); i += 256) {
            int lr = i / (SK_ / 2), w = i % (SK_ / 2);
            srows[lr * 21 + w] = gs[(size_t)(c * CHUNK_ + lr) * (SK_ / 2) + w];
        }
    }

    // Stage q-chunk into kt (coalesced), read own row rotated into regs
    {
        const float4* qg = (const float4*)q;
        for (int i = t; i < CHUNK_ * 16; i += 256) {
            int lr = i >> 4, j = i & 15;
            ((float4*)kt)[lr * 16 + j] =
                qg[(size_t)((b * L_ + (c * CHUNK_ + lr)) * H_ + h) * 16 + j];
        }
    }
    __syncthreads();

    ulonglong2 qreg[16];
    {
        const ulonglong2* kt2 = (const ulonglong2*)kt;
        #pragma unroll
        for (int i = 0; i < 16; i++)
            qreg[i] = kt2[t * 16 + ((i + lane) & 15)];
    }

    const unsigned short* srow = sidx + t * 42;
    const float4* kg = (const float4*)k;
    float mx = -CUDART_INF_F, sm = 0.f;
    int p = 0;

    for (int s0 = 0; s0 < S_; s0 += TILE2_) {
        __syncthreads();
        for (int i = t; i < TILE2_ * 16; i += 256) {
            int r = i >> 4, j = i & 15;
            ((float4*)kt)[r * 16 + j] =
                kg[(size_t)((b * S_ + (s0 + r)) * H_ + h) * 16 + j];
        }
        __syncthreads();

        const ulonglong2* kt2 = (const ulonglong2*)kt;
        while (p < SK_) {
            int s = srow[p];
            if (s >= s0 + TILE2_) break;
            const ulonglong2* kr = kt2 + (s - s0) * 16;

            // 4 independent accumulators; loads batched ahead of FMAs.
            unsigned long long a0 = 0ull, a1 = 0ull, a2 = 0ull, a3 = 0ull;
            #pragma unroll
            for (int i = 0; i < 16; i += 4) {
                ulonglong2 k0 = kr[((i + 0 + lane) & 15)];
                ulonglong2 k1 = kr[((i + 1 + lane) & 15)];
                ulonglong2 k2 = kr[((i + 2 + lane) & 15)];
                ulonglong2 k3 = kr[((i + 3 + lane) & 15)];
                a0 = ffma2(qreg[i + 0].x, k0.x, a0);
                a1 = ffma2(qreg[i + 1].x, k1.x, a1);
                a2 = ffma2(qreg[i + 2].x, k2.x, a2);
                a3 = ffma2(qreg[i + 3].x, k3.x, a3);
                a0 = ffma2(qreg[i + 0].y, k0.y, a0);
                a1 = ffma2(qreg[i + 1].y, k1.y, a1);
                a2 = ffma2(qreg[i + 2].y, k2.y, a2);
                a3 = ffma2(qreg[i + 3].y, k3.y, a3);
            }
            float acc = f32x2_sum(addf2(addf2(a0, a1), addf2(a2, a3)));
            mx = fmaxf(mx, acc);
            sm += acc;
            p++;
        }
    }

    g_M[(size_t)(b * H_ + h) * L_ + c * CHUNK_ + t] =
        mx - sm * (1.0f / (float)S_);
}

// ---------------------------------------------------------------------------
// K2: top-40 per (b,h). One WARP per bh; 64 vals/lane register-resident.
// ---------------------------------------------------------------------------
__global__ __launch_bounds__(512) void k_topk() {
    const int w = (blockIdx.x << 4) + (threadIdx.x >> 5);
    const int lane = threadIdx.x & 31;

    float vals[64];
    #pragma unroll
    for (int j = 0; j < 64; j++)
        vals[j] = g_M[(size_t)w * L_ + j * 32 + lane];

    unsigned long long mask = 0ull;
    float bv = -CUDART_INF_F; int bj = 0;
    #pragma unroll
    for (int j = 0; j < 64; j++)
        if (vals[j] > bv) { bv = vals[j]; bj = j; }

    for (int it = 0; it < NTOP_; it++) {
        unsigned long long key =
            ((unsigned long long)ford(bv) << 32) |
            (unsigned)~(unsigned)(bj * 32 + lane);
        #pragma unroll
        for (int o = 16; o; o >>= 1) {
            unsigned long long ot = __shfl_xor_sync(0xFFFFFFFFu, key, o);
            if (ot > key) key = ot;
        }
        unsigned widx = ~(unsigned)(key & 0xFFFFFFFFu);
        if (lane == 0) g_top[w * NTOP_ + it] = (int)widx;
        if ((widx & 31u) == (unsigned)lane) {
            mask |= 1ull << (widx >> 5);
            bv = -CUDART_INF_F; bj = 0;
            #pragma unroll
            for (int j = 0; j < 64; j++)
                if (!((mask >> j) & 1ull) && vals[j] > bv) { bv = vals[j]; bj = j; }
        }
    }
}

// ---------------------------------------------------------------------------
// K3: vmean[bh, d] = mean_s v[b,s,h,d]
// ---------------------------------------------------------------------------
__global__ void k_vmean(const float* __restrict__ v) {
    int bh = blockIdx.x;
    int b = bh >> 3, h = bh & 7;
    int tid = threadIdx.x;
    int d = tid & 63, g = tid >> 6;
    float s = 0.f;
    #pragma unroll 4
    for (int r = g; r < S_; r += 4)
        s += v[(((size_t)(b * S_ + r)) * H_ + h) * D_ + d];
    __shared__ float part[4][D_];
    part[g][d] = s;
    __syncthreads();
    if (g == 0)
        g_vmean[bh * D_ + d] =
            (part[0][d] + part[1][d] + part[2][d] + part[3][d]) * (1.0f / (float)S_);
}

// ---------------------------------------------------------------------------
// K4: out[b,l,h,d] = vmean[bh,d]
// ---------------------------------------------------------------------------
__global__ void k_fill(float4* __restrict__ out) {
    unsigned i = blockIdx.x * blockDim.x + threadIdx.x;
    if (i >= (unsigned)(B_ * L_ * H_ * (D_ / 4))) return;
    unsigned d4 = i & 15u;
    unsigned h  = (i >> 4) & 7u;
    unsigned b  = i >> 18;
    const float4* vm = (const float4*)g_vmean;
    out[i] = __ldg(vm + ((b * H_ + h) * (D_ / 4) + d4));
}

// ---------------------------------------------------------------------------
// K5: dense attention (R10-proven): 4 queries/block, 320 blocks,
// smem-tiled K scores, warp softmax, coalesced AV.
// ---------------------------------------------------------------------------
#define SMEM_ATTN_ (ATILE_ * D_ * 4)

__global__ __launch_bounds__(256) void k_attn(const float* __restrict__ q,
                                              const float* __restrict__ k,
                                              const float* __restrict__ v,
                                              float* __restrict__ out) {
    extern __shared__ float k_t[];
    int bh = blockIdx.x / QBLKS_;
    int qb = blockIdx.x % QBLKS_;
    int b = bh >> 3, h = bh & 7;
    int tid = threadIdx.x;

    __shared__ float sq[QPB_][D_];
    __shared__ float sc[QPB_][S_];
    __shared__ float sZ[QPB_];
    __shared__ int   sl[QPB_];
    __shared__ float pr[4][QPB_][D_];

    if (tid < QPB_ * D_) {
        int qi = tid >> 6, d = tid & 63;
        int lsel = g_top[bh * NTOP_ + qb * QPB_ + qi];
        if (d == 0) sl[qi] = lsel;
        sq[qi][d] = q[(((size_t)(b * L_ + lsel)) * H_ + h) * D_ + d] * SCALE_;
    }
    __syncthreads();

    const float4* kg = (const float4*)k;
    for (int s0 = 0; s0 < S_; s0 += ATILE_) {
        __syncthreads();
        for (int i = tid; i < ATILE_ * 16; i += 256) {
            int r = i >> 4, j = i & 15;
            ((float4*)k_t)[r * 16 + (j ^ (r & 15))] =
                kg[(size_t)((b * S_ + (s0 + r)) * H_ + h) * 16 + j];
        }
        __syncthreads();

        int r = tid;
        const float4* kr = (const float4*)k_t + r * 16;
        const float4* q0 = (const float4*)sq[0];
        const float4* q1 = (const float4*)sq[1];
        const float4* q2 = (const float4*)sq[2];
        const float4* q3 = (const float4*)sq[3];
        float a0 = 0.f, a1 = 0.f, a2 = 0.f, a3 = 0.f;
        #pragma unroll
        for (int j = 0; j < 16; j++) {
            float4 kv = kr[j ^ (r & 15)];
            float4 qa = q0[j];
            a0 += qa.x * kv.x + qa.y * kv.y + qa.z * kv.z + qa.w * kv.w;
            float4 qc = q1[j];
            a1 += qc.x * kv.x + qc.y * kv.y + qc.z * kv.z + qc.w * kv.w;
            float4 qd = q2[j];
            a2 += qd.x * kv.x + qd.y * kv.y + qd.z * kv.z + qd.w * kv.w;
            float4 qe = q3[j];
            a3 += qe.x * kv.x + qe.y * kv.y + qe.z * kv.z + qe.w * kv.w;
        }
        sc[0][s0 + r] = a0;
        sc[1][s0 + r] = a1;
        sc[2][s0 + r] = a2;
        sc[3][s0 + r] = a3;
    }
    __syncthreads();

    int w = tid >> 5, lane = tid & 31;
    if (w < QPB_) {
        float mx = -CUDART_INF_F;
        for (int s = lane; s < S_; s += 32) mx = fmaxf(mx, sc[w][s]);
        #pragma unroll
        for (int o = 16; o; o >>= 1) mx = fmaxf(mx, __shfl_xor_sync(0xFFFFFFFFu, mx, o));
        float sum = 0.f;
        for (int s = lane; s < S_; s += 32) {
            float e = __expf(sc[w][s] - mx);
            sc[w][s] = e;
            sum += e;
        }
        #pragma unroll
        for (int o = 16; o; o >>= 1) sum += __shfl_xor_sync(0xFFFFFFFFu, sum, o);
        if (lane == 0) sZ[w] = sum;
    }
    __syncthreads();

    int d = tid & 63, g = tid >> 6;
    float acc[QPB_] = {0.f, 0.f, 0.f, 0.f};
    #pragma unroll 4
    for (int s = g; s < S_; s += 4) {
        float vv = v[(((size_t)(b * S_ + s)) * H_ + h) * D_ + d];
        #pragma unroll
        for (int qi = 0; qi < QPB_; qi++) acc[qi] += sc[qi][s] * vv;
    }
    #pragma unroll
    for (int qi = 0; qi < QPB_; qi++) pr[g][qi][d] = acc[qi];
    __syncthreads();
    if (g < QPB_) {
        int qi = g;
        float r = (pr[0][qi][d] + pr[1][qi][d] + pr[2][qi][d] + pr[3][qi][d]) / sZ[qi];
        out[(((size_t)(b * L_ + sl[qi])) * H_ + h) * D_ + d] = r;
    }
}

// ---------------------------------------------------------------------------
extern "C" void kernel_launch(void* const* d_in, const int* in_sizes, int n_in,
                              void* d_out, int out_size) {
    const float* q   = (const float*)d_in[0];
    const float* k   = (const float*)d_in[1];
    const float* v   = (const float*)d_in[2];
    const int*   idx = (const int*)d_in[3];
    float* out = (float*)d_out;

    cudaFuncSetAttribute(k_sample, cudaFuncAttributeMaxDynamicSharedMemorySize,
                         SMEM_SAMPLE_);
    cudaFuncSetAttribute(k_attn, cudaFuncAttributeMaxDynamicSharedMemorySize,
                         SMEM_ATTN_);

    // 1: vmean  2: fill  3: sort  4: sample (ncu capture slot)  5: topk  6: attn
    k_vmean<<<BH_, 256>>>(v);
    {
        unsigned n4 = B_ * L_ * H_ * (D_ / 4);
        k_fill<<<(n4 + 255) / 256, 256>>>((float4*)out);
    }
    k_sort<<<L_ / 8, 256>>>(idx);
    k_sample<<<B_ * H_ * NCHUNK_, 256, SMEM_SAMPLE_>>>(q, k);
    k_topk<<<2, 512>>>();
    k_attn<<<BH_ * QBLKS_, 256, SMEM_ATTN_>>>(q, k, v, out);
}

// round 16
// speedup vs baseline: 1.9617x; 1.2742x over previous
#include <cuda_runtime.h>
#include <cuda_bf16.h>
#include <math_constants.h>

// ProbAttention (Informer ProbSparse) — B=4, L=S=2048, H=8, D=64, sample_k=n_top=40.
// Inputs: queries f32 [B,L,H,D], keys f32 [B,S,H,D], values f32 [B,S,H,D],
//         index_sample i32 [L,40].  Output f32 [B,L,H,D].

#define B_ 4
#define L_ 2048
#define S_ 2048
#define H_ 8
#define D_ 64
#define SK_ 40
#define NTOP_ 40
#define BH_ (B_ * H_)
#define SCALE_ 0.125f
#define QPB_ 8
#define QBLKS_ (NTOP_ / QPB_)        // 5

#define CHUNK_ 256
#define NCHUNK_ (L_ / CHUNK_)        // 8
#define TILE2_ 256                   // k-rows per smem tile (k_sample)
#define ATILE_ 128                   // k-rows per smem tile (k_attn)

// Scratch
__device__ unsigned short g_sorted[L_ * SK_];   // per-l samples, ascending s
__device__ float g_M[BH_ * L_];
__device__ int   g_top[BH_ * NTOP_];
__device__ float g_vpart[8 * BH_ * D_];         // vmean partials (8 s-splits)

// Order-preserving float->uint (topk packing)
__device__ __forceinline__ unsigned ford(float f) {
    unsigned u = __float_as_uint(f);
    return (u & 0x80000000u) ? ~u : (u | 0x80000000u);
}

// Packed f32x2 helpers (Blackwell)
__device__ __forceinline__ unsigned long long ffma2(unsigned long long a,
                                                    unsigned long long b,
                                                    unsigned long long c) {
    unsigned long long d;
    asm("fma.rn.f32x2 %0, %1, %2, %3;" : "=l"(d) : "l"(a), "l"(b), "l"(c));
    return d;
}
__device__ __forceinline__ unsigned long long addf2(unsigned long long a,
                                                    unsigned long long b) {
    unsigned long long d;
    asm("add.rn.f32x2 %0, %1, %2;" : "=l"(d) : "l"(a), "l"(b));
    return d;
}
__device__ __forceinline__ float f32x2_sum(unsigned long long v) {
    float lo, hi;
    asm("mov.b64 {%0, %1}, %2;" : "=f"(lo), "=f"(hi) : "l"(v));
    return lo + hi;
}

// ---------------------------------------------------------------------------
// K_sort: one WARP per l. Stable rank sort of 40 sample indices -> ascending.
// ---------------------------------------------------------------------------
__global__ __launch_bounds__(256) void k_sort(const int* __restrict__ idxs) {
    const int l = (blockIdx.x << 3) + (threadIdx.x >> 5);
    const int lane = threadIdx.x & 31;

    int s0v = idxs[l * SK_ + lane];
    int s1v = (lane < SK_ - 32) ? idxs[l * SK_ + 32 + lane] : 0x7FFFFFFF;

    int r0 = 0, r1 = 0;
    #pragma unroll
    for (int v = 0; v < SK_; v++) {
        int sv = __shfl_sync(0xFFFFFFFFu, (v < 32) ? s0v : s1v, v & 31);
        r0 += (sv < s0v) || (sv == s0v && v < lane);
        r1 += (sv < s1v) || (sv == s1v && v < 32 + lane);
    }
    unsigned short* row = g_sorted + l * SK_;
    row[r0] = (unsigned short)s0v;
    if (lane < SK_ - 32) row[r1] = (unsigned short)s1v;
}

// ---------------------------------------------------------------------------
// K1 (R15-proven): block = (b,h,chunk); thread t owns l = chunk*256+t.
// q-row in registers; K streamed in 256-row smem tiles; conflict-free
// random-row LDS via (i+lane)&15 rotation; 4 independent f32x2 accumulators.
// ---------------------------------------------------------------------------
#define SMEM_SAMPLE_ (TILE2_ * D_ * 4 + CHUNK_ * 42 * 2)

__global__ __launch_bounds__(256) void k_sample(const float* __restrict__ q,
                                                const float* __restrict__ k) {
    extern __shared__ float dyn[];
    float* kt = dyn;                                             // [256][64]
    unsigned short* sidx = (unsigned short*)(dyn + TILE2_ * D_); // [256][42]

    const int bhc = blockIdx.x;
    const int c = bhc & 7, h = (bhc >> 3) & 7, b = bhc >> 6;
    const int t = threadIdx.x;
    const int lane = t & 31;

    {
        const unsigned* gs = (const unsigned*)g_sorted;
        unsigned* srows = (unsigned*)sidx;
        for (int i = t; i < CHUNK_ * (SK_ / 2); i += 256) {
            int lr = i / (SK_ / 2), w = i % (SK_ / 2);
            srows[lr * 21 + w] = gs[(size_t)(c * CHUNK_ + lr) * (SK_ / 2) + w];
        }
    }

    {
        const float4* qg = (const float4*)q;
        for (int i = t; i < CHUNK_ * 16; i += 256) {
            int lr = i >> 4, j = i & 15;
            ((float4*)kt)[lr * 16 + j] =
                qg[(size_t)((b * L_ + (c * CHUNK_ + lr)) * H_ + h) * 16 + j];
        }
    }
    __syncthreads();

    ulonglong2 qreg[16];
    {
        const ulonglong2* kt2 = (const ulonglong2*)kt;
        #pragma unroll
        for (int i = 0; i < 16; i++)
            qreg[i] = kt2[t * 16 + ((i + lane) & 15)];
    }

    const unsigned short* srow = sidx + t * 42;
    const float4* kg = (const float4*)k;
    float mx = -CUDART_INF_F, sm = 0.f;
    int p = 0;

    for (int s0 = 0; s0 < S_; s0 += TILE2_) {
        __syncthreads();
        for (int i = t; i < TILE2_ * 16; i += 256) {
            int r = i >> 4, j = i & 15;
            ((float4*)kt)[r * 16 + j] =
                kg[(size_t)((b * S_ + (s0 + r)) * H_ + h) * 16 + j];
        }
        __syncthreads();

        const ulonglong2* kt2 = (const ulonglong2*)kt;
        while (p < SK_) {
            int s = srow[p];
            if (s >= s0 + TILE2_) break;
            const ulonglong2* kr = kt2 + (s - s0) * 16;

            unsigned long long a0 = 0ull, a1 = 0ull, a2 = 0ull, a3 = 0ull;
            #pragma unroll
            for (int i = 0; i < 16; i += 4) {
                ulonglong2 k0 = kr[((i + 0 + lane) & 15)];
                ulonglong2 k1 = kr[((i + 1 + lane) & 15)];
                ulonglong2 k2 = kr[((i + 2 + lane) & 15)];
                ulonglong2 k3 = kr[((i + 3 + lane) & 15)];
                a0 = ffma2(qreg[i + 0].x, k0.x, a0);
                a1 = ffma2(qreg[i + 1].x, k1.x, a1);
                a2 = ffma2(qreg[i + 2].x, k2.x, a2);
                a3 = ffma2(qreg[i + 3].x, k3.x, a3);
                a0 = ffma2(qreg[i + 0].y, k0.y, a0);
                a1 = ffma2(qreg[i + 1].y, k1.y, a1);
                a2 = ffma2(qreg[i + 2].y, k2.y, a2);
                a3 = ffma2(qreg[i + 3].y, k3.y, a3);
            }
            float acc = f32x2_sum(addf2(addf2(a0, a1), addf2(a2, a3)));
            mx = fmaxf(mx, acc);
            sm += acc;
            p++;
        }
    }

    g_M[(size_t)(b * H_ + h) * L_ + c * CHUNK_ + t] =
        mx - sm * (1.0f / (float)S_);
}

// ---------------------------------------------------------------------------
// K2: top-40 per (b,h). One WARP per bh; 64 vals/lane register-resident.
// ---------------------------------------------------------------------------
__global__ __launch_bounds__(512) void k_topk() {
    const int w = (blockIdx.x << 4) + (threadIdx.x >> 5);
    const int lane = threadIdx.x & 31;

    float vals[64];
    #pragma unroll
    for (int j = 0; j < 64; j++)
        vals[j] = g_M[(size_t)w * L_ + j * 32 + lane];

    unsigned long long mask = 0ull;
    float bv = -CUDART_INF_F; int bj = 0;
    #pragma unroll
    for (int j = 0; j < 64; j++)
        if (vals[j] > bv) { bv = vals[j]; bj = j; }

    for (int it = 0; it < NTOP_; it++) {
        unsigned long long key =
            ((unsigned long long)ford(bv) << 32) |
            (unsigned)~(unsigned)(bj * 32 + lane);
        #pragma unroll
        for (int o = 16; o; o >>= 1) {
            unsigned long long ot = __shfl_xor_sync(0xFFFFFFFFu, key, o);
            if (ot > key) key = ot;
        }
        unsigned widx = ~(unsigned)(key & 0xFFFFFFFFu);
        if (lane == 0) g_top[w * NTOP_ + it] = (int)widx;
        if ((widx & 31u) == (unsigned)lane) {
            mask |= 1ull << (widx >> 5);
            bv = -CUDART_INF_F; bj = 0;
            #pragma unroll
            for (int j = 0; j < 64; j++)
                if (!((mask >> j) & 1ull) && vals[j] > bv) { bv = vals[j]; bj = j; }
        }
    }
}

// ---------------------------------------------------------------------------
// K3: vmean partials — 256 blocks (bh x 8 s-splits), NO atomics.
// g_vpart[split][bh][d] = sum over that split's 256 rows.
// ---------------------------------------------------------------------------
__global__ void k_vmean(const float* __restrict__ v) {
    int bh = blockIdx.x >> 3, split = blockIdx.x & 7;
    int b = bh >> 3, h = bh & 7;
    int tid = threadIdx.x;
    int d = tid & 63, g = tid >> 6;
    int r0 = split * 256;
    float s = 0.f;
    #pragma unroll 4
    for (int r = r0 + g; r < r0 + 256; r += 4)
        s += v[(((size_t)(b * S_ + r)) * H_ + h) * D_ + d];
    __shared__ float part[4][D_];
    part[g][d] = s;
    __syncthreads();
    if (g == 0)
        g_vpart[(split * BH_ + bh) * D_ + d] =
            part[0][d] + part[1][d] + part[2][d] + part[3][d];
}

// ---------------------------------------------------------------------------
// K4: out[b,l,h,d] = mean = (1/S) * sum of 8 partials (reduced here).
// ---------------------------------------------------------------------------
__global__ void k_fill(float4* __restrict__ out) {
    unsigned i = blockIdx.x * blockDim.x + threadIdx.x;
    if (i >= (unsigned)(B_ * L_ * H_ * (D_ / 4))) return;
    unsigned d4 = i & 15u;
    unsigned h  = (i >> 4) & 7u;
    unsigned b  = i >> 18;
    unsigned bh = b * H_ + h;
    const float4* vp = (const float4*)g_vpart;
    float4 a = vp[(0 * BH_ + bh) * 16 + d4];
    #pragma unroll
    for (int sp = 1; sp < 8; sp++) {
        float4 p = vp[(sp * BH_ + bh) * 16 + d4];
        a.x += p.x; a.y += p.y; a.z += p.z; a.w += p.w;
    }
    const float inv = 1.0f / (float)S_;
    a.x *= inv; a.y *= inv; a.z *= inv; a.w *= inv;
    out[i] = a;
}

// ---------------------------------------------------------------------------
// K5: dense attention, QPB=8, 160 blocks (single wave at 2 blocks/SM).
// Scores: K tiled 128 rows; thread = (row, query-half of 4).
// Softmax: 8 warps, one query each. AV: 8 FMA per v-load.
// Dyn smem: k_t 32KB + sc 64KB = 96KB.
// ---------------------------------------------------------------------------
#define SMEM_ATTN_ ((ATILE_ * D_ + QPB_ * S_) * 4)

__global__ __launch_bounds__(256) void k_attn(const float* __restrict__ q,
                                              const float* __restrict__ k,
                                              const float* __restrict__ v,
                                              float* __restrict__ out) {
    extern __shared__ float dyn[];
    float* k_t = dyn;                  // [ATILE_][16 float4] swizzled
    float* sc  = dyn + ATILE_ * D_;    // [QPB_][S_]

    __shared__ __align__(16) float sq[QPB_][D_];
    __shared__ float sZ[QPB_];
    __shared__ int   sl[QPB_];
    __shared__ float pr[4][QPB_][D_];

    const int bh = blockIdx.x / QBLKS_;
    const int qb = blockIdx.x % QBLKS_;
    const int b = bh >> 3, h = bh & 7;
    const int tid = threadIdx.x;

    for (int i = tid; i < QPB_ * D_; i += 256) {
        int qi = i >> 6, d = i & 63;
        int lsel = g_top[bh * NTOP_ + qb * QPB_ + qi];
        if (d == 0) sl[qi] = lsel;
        sq[qi][d] = q[(((size_t)(b * L_ + lsel)) * H_ + h) * D_ + d] * SCALE_;
    }
    __syncthreads();

    // Scores: 128-row tiles; thread = (row r, query-half qh of 4 queries)
    const float4* kg = (const float4*)k;
    const int r  = tid & (ATILE_ - 1);
    const int qh = tid >> 7;                 // 0 or 1
    for (int s0 = 0; s0 < S_; s0 += ATILE_) {
        __syncthreads();
        for (int i = tid; i < ATILE_ * 16; i += 256) {
            int rr = i >> 4, j = i & 15;
            ((float4*)k_t)[rr * 16 + (j ^ (rr & 15))] =
                kg[(size_t)((b * S_ + (s0 + rr)) * H_ + h) * 16 + j];
        }
        __syncthreads();

        const float4* kr = (const float4*)k_t + r * 16;
        const float4* q0 = (const float4*)sq[qh * 4 + 0];
        const float4* q1 = (const float4*)sq[qh * 4 + 1];
        const float4* q2 = (const float4*)sq[qh * 4 + 2];
        const float4* q3 = (const float4*)sq[qh * 4 + 3];
        float a0 = 0.f, a1 = 0.f, a2 = 0.f, a3 = 0.f;
        #pragma unroll
        for (int j = 0; j < 16; j++) {
            float4 kv = kr[j ^ (r & 15)];
            float4 qa = q0[j];
            a0 += qa.x * kv.x + qa.y * kv.y + qa.z * kv.z + qa.w * kv.w;
            float4 qc = q1[j];
            a1 += qc.x * kv.x + qc.y * kv.y + qc.z * kv.z + qc.w * kv.w;
            float4 qd = q2[j];
            a2 += qd.x * kv.x + qd.y * kv.y + qd.z * kv.z + qd.w * kv.w;
            float4 qe = q3[j];
            a3 += qe.x * kv.x + qe.y * kv.y + qe.z * kv.z + qe.w * kv.w;
        }
        sc[(qh * 4 + 0) * S_ + s0 + r] = a0;
        sc[(qh * 4 + 1) * S_ + s0 + r] = a1;
        sc[(qh * 4 + 2) * S_ + s0 + r] = a2;
        sc[(qh * 4 + 3) * S_ + s0 + r] = a3;
    }
    __syncthreads();

    // Softmax: warp w owns query w (all 8 warps active)
    const int w = tid >> 5, lane = tid & 31;
    {
        float mx = -CUDART_INF_F;
        for (int s = lane; s < S_; s += 32) mx = fmaxf(mx, sc[w * S_ + s]);
        #pragma unroll
        for (int o = 16; o; o >>= 1) mx = fmaxf(mx, __shfl_xor_sync(0xFFFFFFFFu, mx, o));
        float sum = 0.f;
        for (int s = lane; s < S_; s += 32) {
            float e = __expf(sc[w * S_ + s] - mx);
            sc[w * S_ + s] = e;
            sum += e;
        }
        #pragma unroll
        for (int o = 16; o; o >>= 1) sum += __shfl_xor_sync(0xFFFFFFFFu, sum, o);
        if (lane == 0) sZ[w] = sum;
    }
    __syncthreads();

    // AV: thread = (d, g); 8 FMA per v-load.
    const int d = tid & 63, g = tid >> 6;
    float acc[QPB_] = {0.f, 0.f, 0.f, 0.f, 0.f, 0.f, 0.f, 0.f};
    #pragma unroll 4
    for (int s = g; s < S_; s += 4) {
        float vv = v[(((size_t)(b * S_ + s)) * H_ + h) * D_ + d];
        #pragma unroll
        for (int qi = 0; qi < QPB_; qi++) acc[qi] += sc[qi * S_ + s] * vv;
    }
    #pragma unroll
    for (int qi = 0; qi < QPB_; qi++) pr[g][qi][d] = acc[qi];
    __syncthreads();

    for (int i = tid; i < QPB_ * D_; i += 256) {
        int qi = i >> 6, dd = i & 63;
        float r4 = (pr[0][qi][dd] + pr[1][qi][dd] + pr[2][qi][dd] + pr[3][qi][dd])
                   / sZ[qi];
        out[(((size_t)(b * L_ + sl[qi])) * H_ + h) * D_ + dd] = r4;
    }
}

// ---------------------------------------------------------------------------
extern "C" void kernel_launch(void* const* d_in, const int* in_sizes, int n_in,
                              void* d_out, int out_size) {
    const float* q   = (const float*)d_in[0];
    const float* k   = (const float*)d_in[1];
    const float* v   = (const float*)d_in[2];
    const int*   idx = (const int*)d_in[3];
    float* out = (float*)d_out;

    cudaFuncSetAttribute(k_sample, cudaFuncAttributeMaxDynamicSharedMemorySize,
                         SMEM_SAMPLE_);
    cudaFuncSetAttribute(k_attn, cudaFuncAttributeMaxDynamicSharedMemorySize,
                         SMEM_ATTN_);

    // 1: vmean  2: fill  3: sort  4: sample (ncu capture slot)  5: topk  6: attn
    k_vmean<<<BH_ * 8, 256>>>(v);
    {
        unsigned n4 = B_ * L_ * H_ * (D_ / 4);
        k_fill<<<(n4 + 255) / 256, 256>>>((float4*)out);
    }
    k_sort<<<L_ / 8, 256>>>(idx);
    k_sample<<<B_ * H_ * NCHUNK_, 256, SMEM_SAMPLE_>>>(q, k);
    k_topk<<<2, 512>>>();
    k_attn<<<BH_ * QBLKS_, 256, SMEM_ATTN_>>>(q, k, v, out);
}